// round 14
// baseline (speedup 1.0000x reference)
#include <cuda_runtime.h>
#include <cuda_fp16.h>

// Problem constants
#define NXv 128
#define NYv 128
#define NZv 8
#define NVOX (NXv * NYv * NZv)   // 131072
#define NVIEW 6
#define NCH 64
#define HFv 116
#define WFv 200
#define FEAT_HW (HFv * WFv)      // 23200
#define IMG_W 1600.0f
#define IMG_H 928.0f

#define PTS_PER_BLK 64           // gather: 2 points per thread
#define INV_OFF 0xFFFFFFFFu

#define CONV_WT ((WFv + 31) / 32)            // 7 w-tiles
#define CONV_BLOCKS (CONV_WT * NVIEW * HFv)  // 4872
#define PROJ_BLOCKS ((NVOX * NVIEW) / 256)   // 3072

// Channel-last fp16 scratch: [V, HF, WF, C]  (17.8 MB). One tap = 128B line.
__device__ __align__(256) static __half g_feat_h[NVIEW * FEAT_HW * NCH];
// Per-(point,view) descriptor: .x = base offset (halves) or INV, .y=(w00,w10),
// .z=(w01,w11) packed fp16, .w unused.  12.6 MB.
__device__ __align__(256) static uint4 g_desc[NVOX * NVIEW];

// ---------------------------------------------------------------------------
// Kernel 1 (fused prep): blocks [0, CONV_BLOCKS) transpose+convert
// [V,C,H,W] fp32 -> [V,H,W,C] fp16; blocks [CONV_BLOCKS, +PROJ_BLOCKS)
// compute one (point,view) descriptor per thread. DRAM-bound convert and
// ALU-bound project overlap inside one launch.
// ---------------------------------------------------------------------------
__global__ __launch_bounds__(256)
void prep_kernel(const float* __restrict__ xfov,
                 const float* __restrict__ points,
                 const float* __restrict__ proj)
{
    __shared__ float tile[NCH][33];
    __shared__ float sM[NVIEW * 16];
    if (threadIdx.x < NVIEW * 16) sM[threadIdx.x] = proj[threadIdx.x];

    if (blockIdx.x < CONV_BLOCKS) {
        // ------------------- convert branch -------------------
        const int bx = blockIdx.x;
        const int w_tile = bx % CONV_WT;
        const int vh = bx / CONV_WT;          // 0..695
        const int v  = vh / HFv;
        const int h  = vh - v * HFv;
        const int w0 = w_tile * 32;

        const int tx = threadIdx.x & 31;
        const int ty = threadIdx.x >> 5;      // 0..7

        const int w = w0 + tx;
        if (w < WFv) {
#pragma unroll
            for (int i = 0; i < 8; i++) {
                const int c = ty + i * 8;
                tile[c][tx] = xfov[((size_t)(v * NCH + c) * HFv + h) * WFv + w];
            }
        }
        __syncthreads();

        __half2* dst = (__half2*)g_feat_h;
#pragma unroll
        for (int j = 0; j < 4; j++) {
            const int ww = w0 + ty + 8 * j;
            if (ww < WFv) {
                const float a = tile[2 * tx + 0][ty + 8 * j];
                const float b = tile[2 * tx + 1][ty + 8 * j];
                dst[(size_t)(v * FEAT_HW + h * WFv + ww) * (NCH / 2) + tx] =
                    __floats2half2_rn(a, b);
            }
        }
    } else {
        // ------------------- project branch -------------------
        __syncthreads();   // sM visible

        const int t = (blockIdx.x - CONV_BLOCKS) * 256 + threadIdx.x; // 0..786431
        const int p = t / NVIEW;
        const int v = t - p * NVIEW;

        // Output-linear p -> (x,y,z); point index n = z*NY*NX + y*NX + x
        const int z = p & (NZv - 1);
        const int y = (p >> 3) & (NYv - 1);
        const int x = p >> 10;
        const int n = (z * NYv + y) * NXv + x;

        const float pxw = __ldg(points + n * 3 + 0);
        const float pyw = __ldg(points + n * 3 + 1);
        const float pzw = __ldg(points + n * 3 + 2);

        const float* M = &sM[v * 16];
        const float cx = fmaf(M[0], pxw, fmaf(M[1], pyw, fmaf(M[2],  pzw, M[3])));
        const float cy = fmaf(M[4], pxw, fmaf(M[5], pyw, fmaf(M[6],  pzw, M[7])));
        const float d  = fmaf(M[8], pxw, fmaf(M[9], pyw, fmaf(M[10], pzw, M[11])));

        const float ds = (fabsf(d) > 1e-6f) ? d : 1e-6f;
        const float r  = __fdividef(1.0f, ds);
        const float u  = cx * r;
        const float vv = cy * r;

        const bool valid = (d > 0.0f) & (u > 0.0f) & (u < IMG_W)
                                      & (vv > 0.0f) & (vv < IMG_H);

        uint4 desc;
        desc.x = INV_OFF; desc.y = 0u; desc.z = 0u; desc.w = 0u;

        if (valid) {
            // Exact power-of-2 scale: WF/IMG_W = HF/IMG_H = 0.125
            const float fx = fmaf(u,  0.125f, -0.5f);   // (-0.5, 199.5)
            const float fy = fmaf(vv, 0.125f, -0.5f);   // (-0.5, 115.5)
            const float x0f = floorf(fx);
            const float y0f = floorf(fy);
            const int x0 = (int)x0f;   // [-1, 199]
            const int y0 = (int)y0f;   // [-1, 115]
            const float wx1 = fx - x0f;
            const float wy1 = fy - y0f;

            // Base clamped so all 4 taps are in-bounds; edge handling folded
            // into weights (identical to zero-padded bilinear).
            const int bx2 = min(max(x0, 0), WFv - 2);
            const int by2 = min(max(y0, 0), HFv - 2);
            const float wl = (x0 < 0) ? wx1 : ((x0 >= WFv - 1) ? 0.0f : 1.0f - wx1);
            const float wr = (x0 < 0) ? 0.0f : ((x0 >= WFv - 1) ? 1.0f - wx1 : wx1);
            const float wt = (y0 < 0) ? wy1 : ((y0 >= HFv - 1) ? 0.0f : 1.0f - wy1);
            const float wb = (y0 < 0) ? 0.0f : ((y0 >= HFv - 1) ? 1.0f - wy1 : wy1);

            const __half2 h0 = __floats2half2_rn(wl * wt, wr * wt); // (w00, w10)
            const __half2 h1 = __floats2half2_rn(wl * wb, wr * wb); // (w01, w11)

            desc.x = (unsigned)((v * FEAT_HW + by2 * WFv + bx2) * NCH);  // halves
            desc.y = *(const unsigned*)&h0;
            desc.z = *(const unsigned*)&h1;
        }
        g_desc[t] = desc;
    }
}

// ---------------------------------------------------------------------------
// Kernel 2: gather. 8 lanes per point, 2 points per thread (block = 64 pts).
// Descriptors read upfront (12 independent broadcast LDG.128), per-lane
// divergent skip, one LDG.128 per tap = 4 points x one full 128B line.
// SMEM-staged coalesced stores.
// ---------------------------------------------------------------------------
__device__ __forceinline__ void view_tap(const uint4 dv, int coff, __half2* acc2)
{
    const __half* bp = g_feat_h + dv.x + coff;

    const uint4 t00 = __ldg((const uint4*)(bp));
    const uint4 t10 = __ldg((const uint4*)(bp + NCH));
    const uint4 t01 = __ldg((const uint4*)(bp + WFv * NCH));
    const uint4 t11 = __ldg((const uint4*)(bp + (WFv + 1) * NCH));

    const __half2 wp0 = *(const __half2*)&dv.y;  // (w00, w10)
    const __half2 wp1 = *(const __half2*)&dv.z;  // (w01, w11)
    const __half2 hw00 = __low2half2(wp0);
    const __half2 hw10 = __high2half2(wp0);
    const __half2 hw01 = __low2half2(wp1);
    const __half2 hw11 = __high2half2(wp1);

    const __half2* f00 = (const __half2*)&t00;
    const __half2* f10 = (const __half2*)&t10;
    const __half2* f01 = (const __half2*)&t01;
    const __half2* f11 = (const __half2*)&t11;
#pragma unroll
    for (int k = 0; k < 4; k++) {
        __half2 s = __hmul2(f00[k], hw00);
        s = __hfma2(f10[k], hw10, s);
        s = __hfma2(f01[k], hw01, s);
        s = __hfma2(f11[k], hw11, s);
        acc2[k] = __hadd2(acc2[k], s);
    }
}

__global__ __launch_bounds__(256)
void gather_kernel(float* __restrict__ out)
{
    __shared__ float s_out[PTS_PER_BLK * 65];   // stride 65: conflict-free

    const int q  = threadIdx.x & 7;            // channel-eighth
    const int pl = threadIdx.x >> 3;           // local point A: 0..31
    const int p0 = blockIdx.x * PTS_PER_BLK;
    const int pA = p0 + pl;
    const int pB = pA + 32;                    // local point B: 32..63
    const int coff = q * 8;                    // channel offset (halves)

    // 12 independent descriptor loads (broadcast across each octet)
    uint4 dA[NVIEW], dB[NVIEW];
#pragma unroll
    for (int v = 0; v < NVIEW; v++) {
        dA[v] = __ldg(&g_desc[pA * NVIEW + v]);
        dB[v] = __ldg(&g_desc[pB * NVIEW + v]);
    }

    int cntA = 0, cntB = 0;
#pragma unroll
    for (int v = 0; v < NVIEW; v++) {
        cntA += (dA[v].x != INV_OFF);
        cntB += (dB[v].x != INV_OFF);
    }

    __half2 accA[4], accB[4];
#pragma unroll
    for (int k = 0; k < 4; k++) {
        accA[k] = __float2half2_rn(0.0f);
        accB[k] = __float2half2_rn(0.0f);
    }

#pragma unroll
    for (int v = 0; v < NVIEW; v++) {
        if (dA[v].x != INV_OFF) view_tap(dA[v], coff, accA);
        if (dB[v].x != INV_OFF) view_tap(dB[v], coff, accB);
    }

    // Stage normalized results in SMEM
    const float invA = (cntA > 0) ? (1.0f / (float)cntA) : 0.0f;
    const float invB = (cntB > 0) ? (1.0f / (float)cntB) : 0.0f;
#pragma unroll
    for (int k = 0; k < 4; k++) {
        const float2 sa = __half22float2(accA[k]);
        const float2 sb = __half22float2(accB[k]);
        s_out[pl * 65 + coff + 2 * k + 0]        = sa.x * invA;
        s_out[pl * 65 + coff + 2 * k + 1]        = sa.y * invA;
        s_out[(pl + 32) * 65 + coff + 2 * k + 0] = sb.x * invB;
        s_out[(pl + 32) * 65 + coff + 2 * k + 1] = sb.y * invB;
    }
    __syncthreads();

    // Coalesced write-out: 4096 floats; 64 consecutive p per channel = 256B
#pragma unroll
    for (int jj = 0; jj < 16; jj++) {
        const int idx = threadIdx.x + jj * 256;   // 0..4095
        const int c   = idx >> 6;                 // 0..63
        const int ppl = idx & 63;                 // 0..63
        out[(size_t)c * NVOX + p0 + ppl] = s_out[ppl * 65 + c];
    }
}

extern "C" void kernel_launch(void* const* d_in, const int* in_sizes, int n_in,
                              void* d_out, int out_size)
{
    const float* x_fov  = (const float*)d_in[0];  // [1,6,64,116,200]
    const float* points = (const float*)d_in[1];  // [131072,3]
    const float* proj   = (const float*)d_in[2];  // [6,4,4]
    float* out = (float*)d_out;                   // [1,64,128,128,8]

    {
        const int blocks = CONV_BLOCKS + PROJ_BLOCKS;  // 7944
        prep_kernel<<<blocks, 256>>>(x_fov, points, proj);
    }
    {
        const int blocks = NVOX / PTS_PER_BLK;         // 2048
        gather_kernel<<<blocks, 256>>>(out);
    }
}

// round 15
// speedup vs baseline: 1.0969x; 1.0969x over previous
#include <cuda_runtime.h>
#include <cuda_fp16.h>

// Problem constants
#define NXv 128
#define NYv 128
#define NZv 8
#define NVOX (NXv * NYv * NZv)   // 131072
#define NVIEW 6
#define NCH 64
#define HFv 116
#define WFv 200
#define FEAT_HW (HFv * WFv)      // 23200
#define IMG_W 1600.0f
#define IMG_H 928.0f

#define PTS_PER_BLK 32           // gather: 1 point per thread (8 lanes/pt)
#define INV_OFF 0xFFFFFFFFu

#define CONV_WT ((WFv + 31) / 32)            // 7 w-tiles
#define CONV_BLOCKS (CONV_WT * NVIEW * HFv)  // 4872
#define PROJ_BLOCKS ((NVOX * NVIEW) / 256)   // 3072

// Channel-last fp16 scratch: [V, HF, WF, C]  (17.8 MB). One tap = 128B line.
__device__ __align__(256) static __half g_feat_h[NVIEW * FEAT_HW * NCH];
// Per-(point,view) descriptor: .x = base offset (halves) or INV, .y=(w00,w10),
// .z=(w01,w11) packed fp16, .w unused.  12.6 MB.
__device__ __align__(256) static uint4 g_desc[NVOX * NVIEW];

// ---------------------------------------------------------------------------
// Kernel 1 (fused prep): blocks [0, CONV_BLOCKS) transpose+convert
// [V,C,H,W] fp32 -> [V,H,W,C] fp16 (float4 global reads); blocks
// [CONV_BLOCKS, +PROJ_BLOCKS) compute one (point,view) descriptor each.
// DRAM-bound convert and ALU-bound project overlap inside one launch.
// ---------------------------------------------------------------------------
__global__ __launch_bounds__(256)
void prep_kernel(const float* __restrict__ xfov,
                 const float* __restrict__ points,
                 const float* __restrict__ proj)
{
    __shared__ float tile[NCH][33];
    __shared__ float sM[NVIEW * 16];
    if (threadIdx.x < NVIEW * 16) sM[threadIdx.x] = proj[threadIdx.x];

    if (blockIdx.x < CONV_BLOCKS) {
        // ------------------- convert branch -------------------
        const int bx = blockIdx.x;
        const int w_tile = bx % CONV_WT;
        const int vh = bx / CONV_WT;          // 0..695
        const int v  = vh / HFv;
        const int h  = vh - v * HFv;
        const int w0 = w_tile * 32;

        // float4 reads: 2 passes x (32 c-rows x 8 float4). 512B/warp/instr.
        {
            const int k = threadIdx.x & 7;            // float4 index in row
            const int cr = threadIdx.x >> 3;          // 0..31
            const int w = w0 + 4 * k;
#pragma unroll
            for (int j = 0; j < 2; j++) {
                const int c = cr + 32 * j;
                if (w < WFv) {   // WFv%4==0, so w<WFv implies w+3<WFv
                    const float4 f = *(const float4*)(
                        xfov + ((size_t)(v * NCH + c) * HFv + h) * WFv + w);
                    tile[c][4 * k + 0] = f.x;
                    tile[c][4 * k + 1] = f.y;
                    tile[c][4 * k + 2] = f.z;
                    tile[c][4 * k + 3] = f.w;
                }
            }
        }
        __syncthreads();

        const int tx = threadIdx.x & 31;
        const int ty = threadIdx.x >> 5;      // 0..7
        __half2* dst = (__half2*)g_feat_h;
#pragma unroll
        for (int j = 0; j < 4; j++) {
            const int ww = w0 + ty + 8 * j;
            if (ww < WFv) {
                const float a = tile[2 * tx + 0][ty + 8 * j];
                const float b = tile[2 * tx + 1][ty + 8 * j];
                dst[(size_t)(v * FEAT_HW + h * WFv + ww) * (NCH / 2) + tx] =
                    __floats2half2_rn(a, b);
            }
        }
    } else {
        // ------------------- project branch -------------------
        __syncthreads();   // sM visible

        const int t = (blockIdx.x - CONV_BLOCKS) * 256 + threadIdx.x; // 0..786431
        const int p = t / NVIEW;
        const int v = t - p * NVIEW;

        // Output-linear p -> (x,y,z); point index n = z*NY*NX + y*NX + x
        const int z = p & (NZv - 1);
        const int y = (p >> 3) & (NYv - 1);
        const int x = p >> 10;
        const int n = (z * NYv + y) * NXv + x;

        const float pxw = __ldg(points + n * 3 + 0);
        const float pyw = __ldg(points + n * 3 + 1);
        const float pzw = __ldg(points + n * 3 + 2);

        const float* M = &sM[v * 16];
        const float cx = fmaf(M[0], pxw, fmaf(M[1], pyw, fmaf(M[2],  pzw, M[3])));
        const float cy = fmaf(M[4], pxw, fmaf(M[5], pyw, fmaf(M[6],  pzw, M[7])));
        const float d  = fmaf(M[8], pxw, fmaf(M[9], pyw, fmaf(M[10], pzw, M[11])));

        const float ds = (fabsf(d) > 1e-6f) ? d : 1e-6f;
        const float r  = __fdividef(1.0f, ds);
        const float u  = cx * r;
        const float vv = cy * r;

        const bool valid = (d > 0.0f) & (u > 0.0f) & (u < IMG_W)
                                      & (vv > 0.0f) & (vv < IMG_H);

        uint4 desc;
        desc.x = INV_OFF; desc.y = 0u; desc.z = 0u; desc.w = 0u;

        if (valid) {
            // Exact power-of-2 scale: WF/IMG_W = HF/IMG_H = 0.125
            const float fx = fmaf(u,  0.125f, -0.5f);   // (-0.5, 199.5)
            const float fy = fmaf(vv, 0.125f, -0.5f);   // (-0.5, 115.5)
            const float x0f = floorf(fx);
            const float y0f = floorf(fy);
            const int x0 = (int)x0f;   // [-1, 199]
            const int y0 = (int)y0f;   // [-1, 115]
            const float wx1 = fx - x0f;
            const float wy1 = fy - y0f;

            // Base clamped so all 4 taps are in-bounds; edge handling folded
            // into weights (identical to zero-padded bilinear).
            const int bx2 = min(max(x0, 0), WFv - 2);
            const int by2 = min(max(y0, 0), HFv - 2);
            const float wl = (x0 < 0) ? wx1 : ((x0 >= WFv - 1) ? 0.0f : 1.0f - wx1);
            const float wr = (x0 < 0) ? 0.0f : ((x0 >= WFv - 1) ? 1.0f - wx1 : wx1);
            const float wt = (y0 < 0) ? wy1 : ((y0 >= HFv - 1) ? 0.0f : 1.0f - wy1);
            const float wb = (y0 < 0) ? 0.0f : ((y0 >= HFv - 1) ? 1.0f - wy1 : wy1);

            const __half2 h0 = __floats2half2_rn(wl * wt, wr * wt); // (w00, w10)
            const __half2 h1 = __floats2half2_rn(wl * wb, wr * wb); // (w01, w11)

            desc.x = (unsigned)((v * FEAT_HW + by2 * WFv + bx2) * NCH);  // halves
            desc.y = *(const unsigned*)&h0;
            desc.z = *(const unsigned*)&h1;
        }
        g_desc[t] = desc;
    }
}

// ---------------------------------------------------------------------------
// Kernel 2: gather. 8 lanes per point, 1 point per thread (block = 32 pts).
// Descriptors read upfront (6 independent broadcast LDG.128), per-lane
// divergent skip, one LDG.128 per tap = 4 points x one full 128B line.
// SMEM-staged coalesced stores. launch_bounds caps regs for occupancy.
// ---------------------------------------------------------------------------
__global__ __launch_bounds__(256, 5)
void gather_kernel(float* __restrict__ out)
{
    __shared__ float s_out[PTS_PER_BLK * 65];   // stride 65: conflict-free

    const int q  = threadIdx.x & 7;            // channel-eighth
    const int pl = threadIdx.x >> 3;           // local point 0..31
    const int p  = blockIdx.x * PTS_PER_BLK + pl;
    const int coff = q * 8;                    // channel offset (halves)

    // Load all 6 descriptors upfront (independent, broadcast across octet)
    const uint4 d0 = __ldg(&g_desc[p * NVIEW + 0]);
    const uint4 d1 = __ldg(&g_desc[p * NVIEW + 1]);
    const uint4 d2 = __ldg(&g_desc[p * NVIEW + 2]);
    const uint4 d3 = __ldg(&g_desc[p * NVIEW + 3]);
    const uint4 d4 = __ldg(&g_desc[p * NVIEW + 4]);
    const uint4 d5 = __ldg(&g_desc[p * NVIEW + 5]);

    const int cnt = (d0.x != INV_OFF) + (d1.x != INV_OFF) + (d2.x != INV_OFF)
                  + (d3.x != INV_OFF) + (d4.x != INV_OFF) + (d5.x != INV_OFF);

    __half2 acc2[4];
#pragma unroll
    for (int k = 0; k < 4; k++) acc2[k] = __float2half2_rn(0.0f);

    const uint4* dsc[NVIEW] = { &d0, &d1, &d2, &d3, &d4, &d5 };

#pragma unroll
    for (int v = 0; v < NVIEW; v++) {
        const uint4 dv = *dsc[v];
        if (dv.x != INV_OFF) {
            const __half* bp = g_feat_h + dv.x + coff;

            const uint4 t00 = __ldg((const uint4*)(bp));
            const uint4 t10 = __ldg((const uint4*)(bp + NCH));
            const uint4 t01 = __ldg((const uint4*)(bp + WFv * NCH));
            const uint4 t11 = __ldg((const uint4*)(bp + (WFv + 1) * NCH));

            const __half2 wp0 = *(const __half2*)&dv.y;  // (w00, w10)
            const __half2 wp1 = *(const __half2*)&dv.z;  // (w01, w11)
            const __half2 hw00 = __low2half2(wp0);
            const __half2 hw10 = __high2half2(wp0);
            const __half2 hw01 = __low2half2(wp1);
            const __half2 hw11 = __high2half2(wp1);

            const __half2* f00 = (const __half2*)&t00;
            const __half2* f10 = (const __half2*)&t10;
            const __half2* f01 = (const __half2*)&t01;
            const __half2* f11 = (const __half2*)&t11;
#pragma unroll
            for (int k = 0; k < 4; k++) {
                __half2 s = __hmul2(f00[k], hw00);
                s = __hfma2(f10[k], hw10, s);
                s = __hfma2(f01[k], hw01, s);
                s = __hfma2(f11[k], hw11, s);
                acc2[k] = __hadd2(acc2[k], s);
            }
        }
    }

    // Stage normalized result in SMEM
    const float inv = (cnt > 0) ? (1.0f / (float)cnt) : 0.0f;
#pragma unroll
    for (int k = 0; k < 4; k++) {
        const float2 sf = __half22float2(acc2[k]);
        s_out[pl * 65 + coff + 2 * k + 0] = sf.x * inv;
        s_out[pl * 65 + coff + 2 * k + 1] = sf.y * inv;
    }
    __syncthreads();

    // Coalesced write-out: 2048 floats; 32 consecutive p per channel = 128B
    const int p0 = blockIdx.x * PTS_PER_BLK;
#pragma unroll
    for (int jj = 0; jj < 8; jj++) {
        const int idx = threadIdx.x + jj * 256;   // 0..2047
        const int c   = idx >> 5;                 // 0..63
        const int ppl = idx & 31;                 // 0..31
        out[(size_t)c * NVOX + p0 + ppl] = s_out[ppl * 65 + c];
    }
}

extern "C" void kernel_launch(void* const* d_in, const int* in_sizes, int n_in,
                              void* d_out, int out_size)
{
    const float* x_fov  = (const float*)d_in[0];  // [1,6,64,116,200]
    const float* points = (const float*)d_in[1];  // [131072,3]
    const float* proj   = (const float*)d_in[2];  // [6,4,4]
    float* out = (float*)d_out;                   // [1,64,128,128,8]

    {
        const int blocks = CONV_BLOCKS + PROJ_BLOCKS;  // 7944
        prep_kernel<<<blocks, 256>>>(x_fov, points, proj);
    }
    {
        const int blocks = NVOX / PTS_PER_BLK;         // 4096
        gather_kernel<<<blocks, 256>>>(out);
    }
}

// round 16
// speedup vs baseline: 1.1167x; 1.0181x over previous
#include <cuda_runtime.h>
#include <cuda_fp16.h>

// Problem constants
#define NXv 128
#define NYv 128
#define NZv 8
#define NVOX (NXv * NYv * NZv)   // 131072
#define NVIEW 6
#define NCH 64
#define HFv 116
#define WFv 200
#define FEAT_HW (HFv * WFv)      // 23200
#define IMG_W 1600.0f
#define IMG_H 928.0f

#define PTS_PER_BLK 32           // gather: 1 point per thread (8 lanes/pt)
#define INV_OFF 0xFFFFFFFFu

#define CONV_WT ((WFv + 31) / 32)            // 7 w-tiles
#define CONV_BLOCKS (CONV_WT * NVIEW * HFv)  // 4872
#define PROJ_BLOCKS ((NVOX * NVIEW) / 256)   // 3072

// Channel-last fp16 scratch: [V, HF, WF, C]  (17.8 MB). One tap = 128B line.
__device__ __align__(256) static __half g_feat_h[NVIEW * FEAT_HW * NCH];
// Per-(point,view) descriptor: .x = base offset (halves) or INV, .y=(w00,w10),
// .z=(w01,w11) packed fp16, .w unused.  12.6 MB.
__device__ __align__(256) static uint4 g_desc[NVOX * NVIEW];

// ---------------------------------------------------------------------------
// Kernel 1 (fused prep): blocks [0, CONV_BLOCKS) transpose+convert
// [V,C,H,W] fp32 -> [V,H,W,C] fp16; blocks [CONV_BLOCKS, +PROJ_BLOCKS)
// compute one (point,view) descriptor per thread. DRAM-bound convert and
// ALU-bound project overlap inside one launch. (Convert = R14 scalar version.)
// ---------------------------------------------------------------------------
__global__ __launch_bounds__(256)
void prep_kernel(const float* __restrict__ xfov,
                 const float* __restrict__ points,
                 const float* __restrict__ proj)
{
    __shared__ float tile[NCH][33];
    __shared__ float sM[NVIEW * 16];
    if (threadIdx.x < NVIEW * 16) sM[threadIdx.x] = proj[threadIdx.x];

    if (blockIdx.x < CONV_BLOCKS) {
        // ------------------- convert branch -------------------
        const int bx = blockIdx.x;
        const int w_tile = bx % CONV_WT;
        const int vh = bx / CONV_WT;          // 0..695
        const int v  = vh / HFv;
        const int h  = vh - v * HFv;
        const int w0 = w_tile * 32;

        const int tx = threadIdx.x & 31;
        const int ty = threadIdx.x >> 5;      // 0..7

        const int w = w0 + tx;
        if (w < WFv) {
#pragma unroll
            for (int i = 0; i < 8; i++) {
                const int c = ty + i * 8;
                tile[c][tx] = xfov[((size_t)(v * NCH + c) * HFv + h) * WFv + w];
            }
        }
        __syncthreads();

        __half2* dst = (__half2*)g_feat_h;
#pragma unroll
        for (int j = 0; j < 4; j++) {
            const int ww = w0 + ty + 8 * j;
            if (ww < WFv) {
                const float a = tile[2 * tx + 0][ty + 8 * j];
                const float b = tile[2 * tx + 1][ty + 8 * j];
                dst[(size_t)(v * FEAT_HW + h * WFv + ww) * (NCH / 2) + tx] =
                    __floats2half2_rn(a, b);
            }
        }
    } else {
        // ------------------- project branch -------------------
        __syncthreads();   // sM visible

        const int t = (blockIdx.x - CONV_BLOCKS) * 256 + threadIdx.x; // 0..786431
        const int p = t / NVIEW;
        const int v = t - p * NVIEW;

        // Output-linear p -> (x,y,z); point index n = z*NY*NX + y*NX + x
        const int z = p & (NZv - 1);
        const int y = (p >> 3) & (NYv - 1);
        const int x = p >> 10;
        const int n = (z * NYv + y) * NXv + x;

        const float pxw = __ldg(points + n * 3 + 0);
        const float pyw = __ldg(points + n * 3 + 1);
        const float pzw = __ldg(points + n * 3 + 2);

        const float* M = &sM[v * 16];
        const float cx = fmaf(M[0], pxw, fmaf(M[1], pyw, fmaf(M[2],  pzw, M[3])));
        const float cy = fmaf(M[4], pxw, fmaf(M[5], pyw, fmaf(M[6],  pzw, M[7])));
        const float d  = fmaf(M[8], pxw, fmaf(M[9], pyw, fmaf(M[10], pzw, M[11])));

        const float ds = (fabsf(d) > 1e-6f) ? d : 1e-6f;
        const float r  = __fdividef(1.0f, ds);
        const float u  = cx * r;
        const float vv = cy * r;

        const bool valid = (d > 0.0f) & (u > 0.0f) & (u < IMG_W)
                                      & (vv > 0.0f) & (vv < IMG_H);

        uint4 desc;
        desc.x = INV_OFF; desc.y = 0u; desc.z = 0u; desc.w = 0u;

        if (valid) {
            // Exact power-of-2 scale: WF/IMG_W = HF/IMG_H = 0.125
            const float fx = fmaf(u,  0.125f, -0.5f);   // (-0.5, 199.5)
            const float fy = fmaf(vv, 0.125f, -0.5f);   // (-0.5, 115.5)
            const float x0f = floorf(fx);
            const float y0f = floorf(fy);
            const int x0 = (int)x0f;   // [-1, 199]
            const int y0 = (int)y0f;   // [-1, 115]
            const float wx1 = fx - x0f;
            const float wy1 = fy - y0f;

            // Base clamped so all 4 taps are in-bounds; edge handling folded
            // into weights (identical to zero-padded bilinear).
            const int bx2 = min(max(x0, 0), WFv - 2);
            const int by2 = min(max(y0, 0), HFv - 2);
            const float wl = (x0 < 0) ? wx1 : ((x0 >= WFv - 1) ? 0.0f : 1.0f - wx1);
            const float wr = (x0 < 0) ? 0.0f : ((x0 >= WFv - 1) ? 1.0f - wx1 : wx1);
            const float wt = (y0 < 0) ? wy1 : ((y0 >= HFv - 1) ? 0.0f : 1.0f - wy1);
            const float wb = (y0 < 0) ? 0.0f : ((y0 >= HFv - 1) ? 1.0f - wy1 : wy1);

            const __half2 h0 = __floats2half2_rn(wl * wt, wr * wt); // (w00, w10)
            const __half2 h1 = __floats2half2_rn(wl * wb, wr * wb); // (w01, w11)

            desc.x = (unsigned)((v * FEAT_HW + by2 * WFv + bx2) * NCH);  // halves
            desc.y = *(const unsigned*)&h0;
            desc.z = *(const unsigned*)&h1;
        }
        g_desc[t] = desc;
    }
}

// ---------------------------------------------------------------------------
// Kernel 2: gather. 8 lanes per point, 1 point per thread (block = 32 pts).
// Block's 192 descriptors staged cooperatively into SMEM (one coalesced
// uint4 per thread + one barrier at block start); per-lane reads are 29cy
// LDS broadcasts instead of ~250cy L2 hits -> tap loads issue early.
// One LDG.128 per tap = 4 points x one full 128B line. SMEM-staged stores.
// ---------------------------------------------------------------------------
__global__ __launch_bounds__(256, 5)
void gather_kernel(float* __restrict__ out)
{
    __shared__ uint4 s_desc[PTS_PER_BLK * NVIEW];  // 3 KB
    __shared__ float s_out[PTS_PER_BLK * 65];      // stride 65: conflict-free

    const int p0 = blockIdx.x * PTS_PER_BLK;

    // Cooperative, coalesced descriptor stage-in (192 x 16B)
    if (threadIdx.x < PTS_PER_BLK * NVIEW)
        s_desc[threadIdx.x] = g_desc[(size_t)p0 * NVIEW + threadIdx.x];
    __syncthreads();

    const int q  = threadIdx.x & 7;            // channel-eighth
    const int pl = threadIdx.x >> 3;           // local point 0..31
    const int coff = q * 8;                    // channel offset (halves)

    int cnt = 0;
#pragma unroll
    for (int v = 0; v < NVIEW; v++)
        cnt += (s_desc[pl * NVIEW + v].x != INV_OFF);

    __half2 acc2[4];
#pragma unroll
    for (int k = 0; k < 4; k++) acc2[k] = __float2half2_rn(0.0f);

#pragma unroll
    for (int v = 0; v < NVIEW; v++) {
        const uint4 dv = s_desc[pl * NVIEW + v];
        if (dv.x != INV_OFF) {
            const __half* bp = g_feat_h + dv.x + coff;

            const uint4 t00 = __ldg((const uint4*)(bp));
            const uint4 t10 = __ldg((const uint4*)(bp + NCH));
            const uint4 t01 = __ldg((const uint4*)(bp + WFv * NCH));
            const uint4 t11 = __ldg((const uint4*)(bp + (WFv + 1) * NCH));

            const __half2 wp0 = *(const __half2*)&dv.y;  // (w00, w10)
            const __half2 wp1 = *(const __half2*)&dv.z;  // (w01, w11)
            const __half2 hw00 = __low2half2(wp0);
            const __half2 hw10 = __high2half2(wp0);
            const __half2 hw01 = __low2half2(wp1);
            const __half2 hw11 = __high2half2(wp1);

            const __half2* f00 = (const __half2*)&t00;
            const __half2* f10 = (const __half2*)&t10;
            const __half2* f01 = (const __half2*)&t01;
            const __half2* f11 = (const __half2*)&t11;
#pragma unroll
            for (int k = 0; k < 4; k++) {
                __half2 s = __hmul2(f00[k], hw00);
                s = __hfma2(f10[k], hw10, s);
                s = __hfma2(f01[k], hw01, s);
                s = __hfma2(f11[k], hw11, s);
                acc2[k] = __hadd2(acc2[k], s);
            }
        }
    }

    // Stage normalized result in SMEM
    const float inv = (cnt > 0) ? (1.0f / (float)cnt) : 0.0f;
#pragma unroll
    for (int k = 0; k < 4; k++) {
        const float2 sf = __half22float2(acc2[k]);
        s_out[pl * 65 + coff + 2 * k + 0] = sf.x * inv;
        s_out[pl * 65 + coff + 2 * k + 1] = sf.y * inv;
    }
    __syncthreads();

    // Coalesced write-out: 2048 floats; 32 consecutive p per channel = 128B
#pragma unroll
    for (int jj = 0; jj < 8; jj++) {
        const int idx = threadIdx.x + jj * 256;   // 0..2047
        const int c   = idx >> 5;                 // 0..63
        const int ppl = idx & 31;                 // 0..31
        out[(size_t)c * NVOX + p0 + ppl] = s_out[ppl * 65 + c];
    }
}

extern "C" void kernel_launch(void* const* d_in, const int* in_sizes, int n_in,
                              void* d_out, int out_size)
{
    const float* x_fov  = (const float*)d_in[0];  // [1,6,64,116,200]
    const float* points = (const float*)d_in[1];  // [131072,3]
    const float* proj   = (const float*)d_in[2];  // [6,4,4]
    float* out = (float*)d_out;                   // [1,64,128,128,8]

    {
        const int blocks = CONV_BLOCKS + PROJ_BLOCKS;  // 7944
        prep_kernel<<<blocks, 256>>>(x_fov, points, proj);
    }
    {
        const int blocks = NVOX / PTS_PER_BLK;         // 4096
        gather_kernel<<<blocks, 256>>>(out);
    }
}